// round 5
// baseline (speedup 1.0000x reference)
#include <cuda_runtime.h>
#include <cuda_bf16.h>
#include <cstdint>
#include <cstddef>

typedef unsigned long long ull;

#define T_   2048
#define B_   128
#define IN_  128
#define H_   256
#define G4_  1024
#define OUT_ 64

#define BG_  16   // batch groups
#define HCN_ 8    // hidden-slice CTAs per batch group
#define BC_  8    // batches per group

#define WPAD 132  // padded row stride (floats) for fp32 GEMM smem tiles

// ---- k_rec smem layout (bytes). Rows padded to 264 bf16 (528B) ----
#define WS_   264                         // bf16 row stride for W/h tiles
#define SM_WHI 0                          // Whi bf16 [128][264]
#define SM_WLO (SM_WHI + 128 * WS_ * 2)   // Wlo
#define SM_HHI (SM_WLO + 128 * WS_ * 2)   // hhi bf16 [8][264]
#define SM_HLO (SM_HHI + 8 * WS_ * 2)     // hlo
#define SM_RED (SM_HLO + 8 * WS_ * 2)     // red f32 [2][8][132]
#define REC_SMEM (SM_RED + 2 * 8 * 132 * 4 + 128)

#define OUT_SMEM ((64 * 256 + 32 * WPAD) * 4)

// ---------------- device scratch (static, allocation-free) ----------------
__device__ float    d_xg[(size_t)T_ * B_ * G4_];    // 1 GB  [t][bg][hc][bb][col]
__device__ float    d_rbuf[(size_t)T_ * B_ * H_];   // 256 MB [t][b][h]
__device__ float    d_hTg[2 * BG_ * H_ * BC_];      // [par][bg][h(k)][bb]
__device__ unsigned d_flags[T_ * BG_ * HCN_];
__device__ unsigned d_runid;

// ---------------- f32x2 helpers ----------------
__device__ __forceinline__ ull pack2(float x) {
    unsigned xi = __float_as_uint(x);
    ull r;
    asm("mov.b64 %0, {%1, %1};" : "=l"(r) : "r"(xi));
    return r;
}
__device__ __forceinline__ ull ffma2(ull a, ull b, ull c) {
    ull d;
    asm("fma.rn.f32x2 %0, %1, %2, %3;" : "=l"(d) : "l"(a), "l"(b), "l"(c));
    return d;
}
__device__ __forceinline__ void unpack2(ull v, float& lo, float& hi) {
    unsigned l, h;
    asm("mov.b64 {%0, %1}, %2;" : "=r"(l), "=r"(h) : "l"(v));
    lo = __uint_as_float(l);
    hi = __uint_as_float(h);
}
__device__ __forceinline__ float sigm(float x) { return 1.0f / (1.0f + __expf(-x)); }

// bf16 mma m16n8k16 row.col, f32 accum (HMMA — works on plain sm_103 target)
__device__ __forceinline__ void mma16816(float& d0, float& d1, float& d2, float& d3,
                                         uint32_t a0, uint32_t a1, uint32_t a2, uint32_t a3,
                                         uint32_t b0, uint32_t b1) {
    asm volatile(
        "mma.sync.aligned.m16n8k16.row.col.f32.bf16.bf16.f32 "
        "{%0,%1,%2,%3}, {%4,%5,%6,%7}, {%8,%9}, {%0,%1,%2,%3};"
        : "+f"(d0), "+f"(d1), "+f"(d2), "+f"(d3)
        : "r"(a0), "r"(a1), "r"(a2), "r"(a3), "r"(b0), "r"(b1));
}

// ---------------- run-id bump ----------------
__global__ void k_init() { d_runid = d_runid + 1u; }

// ---------------- kernel 1: xg = x @ W_ih^T + b_ih + b_hh (permuted) -------
__global__ __launch_bounds__(256, 2) void k_xg(const float* __restrict__ x,
                                               const float* __restrict__ W_ih,
                                               const float* __restrict__ b_ih,
                                               const float* __restrict__ b_hh) {
    __shared__ float xs[32 * WPAD];
    __shared__ float ws[32 * WPAD];
    const int hc = blockIdx.x;
    const int t = blockIdx.y;
    const int u = threadIdx.x;
    const int tm = u & 15;
    const int tn = u >> 4;

    ull acc[8][4];
#pragma unroll
    for (int j = 0; j < 8; j++)
#pragma unroll
        for (int p = 0; p < 4; p++) acc[j][p] = 0ull;

    const int bs = u >> 1, half = u & 1;
    const int colS = u >> 1;
    const int RS = (colS & 3) * H_ + hc * 32 + (colS >> 2);
    const float* xsrc = x + ((size_t)t * B_ + bs) * IN_ + half * 16;
    const float* wsrc = W_ih + (size_t)RS * IN_ + half * 16;

    for (int kc = 0; kc < IN_; kc += 32) {
#pragma unroll
        for (int q = 0; q < 4; q++) {
            float4 v = *(const float4*)(xsrc + kc + q * 4);
            int kl = half * 16 + q * 4;
            xs[(kl + 0) * WPAD + bs] = v.x;
            xs[(kl + 1) * WPAD + bs] = v.y;
            xs[(kl + 2) * WPAD + bs] = v.z;
            xs[(kl + 3) * WPAD + bs] = v.w;
            float4 w = *(const float4*)(wsrc + kc + q * 4);
            ws[(kl + 0) * WPAD + colS] = w.x;
            ws[(kl + 1) * WPAD + colS] = w.y;
            ws[(kl + 2) * WPAD + colS] = w.z;
            ws[(kl + 3) * WPAD + colS] = w.w;
        }
        __syncthreads();
#pragma unroll 8
        for (int kk = 0; kk < 32; kk++) {
            const float* xr = &xs[kk * WPAD + tm * 8];
            ulonglong2 xa = *(const ulonglong2*)xr;
            ulonglong2 xb = *(const ulonglong2*)(xr + 4);
            ull xp0 = xa.x, xp1 = xa.y, xp2 = xb.x, xp3 = xb.y;
            const float* wr = &ws[kk * WPAD + tn * 8];
            float4 wa = *(const float4*)wr;
            float4 wb = *(const float4*)(wr + 4);
            float wv[8] = {wa.x, wa.y, wa.z, wa.w, wb.x, wb.y, wb.z, wb.w};
#pragma unroll
            for (int j = 0; j < 8; j++) {
                ull wj = pack2(wv[j]);
                acc[j][0] = ffma2(wj, xp0, acc[j][0]);
                acc[j][1] = ffma2(wj, xp1, acc[j][1]);
                acc[j][2] = ffma2(wj, xp2, acc[j][2]);
                acc[j][3] = ffma2(wj, xp3, acc[j][3]);
            }
        }
        __syncthreads();
    }
    size_t base = (((size_t)t * BG_ + tm) * HCN_ + hc) * 1024;
#pragma unroll
    for (int j = 0; j < 8; j++) {
        int col = tn * 8 + j;
        int R = (col & 3) * H_ + hc * 32 + (col >> 2);
        float bv = b_ih[R] + b_hh[R];
#pragma unroll
        for (int p = 0; p < 4; p++) {
            float lo, hi;
            unpack2(acc[j][p], lo, hi);
            d_xg[base + (size_t)(2 * p) * 128 + col] = lo + bv;
            d_xg[base + (size_t)(2 * p + 1) * 128 + col] = hi + bv;
        }
    }
}

// ---------------- kernel 2: persistent recurrence (HMMA core) ----------------
// 128 CTAs: blockIdx.x = bg*8 + hc. CTA owns gate-rows r = hh*4+g for its 32
// hidden units (hc*32..+31), batches bg*8..+7.
// Per step: D[128x8] = W[128x256] @ h[256x8] via mma.sync bf16 3-term split.
// 16 warps = 8 M-tiles x 2 K-halves; partials merged through smem red[2].
__global__ __launch_bounds__(512, 1) void k_rec(const float* __restrict__ W_hh) {
    extern __shared__ char smem[];
    float* red = (float*)(smem + SM_RED);   // [2][8][132]

    const int u = threadIdx.x;
    const int wid = u >> 5;
    const int lane = u & 31;
    const int g = lane >> 2, tg = lane & 3;
    const int bg = blockIdx.x >> 3;
    const int hc = blockIdx.x & 7;
    const unsigned runid = d_runid;

    // --- stage W slice once: smem row r = hh*4+g_gate <- W_hh row (g_gate*256 + hc*32 + hh),
    //     split into bf16 hi/lo, row-major k with WS_ pad ---
    {
        int r = u >> 2;
        int k0 = (u & 3) * 64;
        int hhw = r >> 2, gw = r & 3;
        const float* src = W_hh + (size_t)(gw * H_ + hc * 32 + hhw) * H_ + k0;
        __nv_bfloat16* whi = (__nv_bfloat16*)(smem + SM_WHI) + (size_t)r * WS_ + k0;
        __nv_bfloat16* wlo = (__nv_bfloat16*)(smem + SM_WLO) + (size_t)r * WS_ + k0;
#pragma unroll 4
        for (int kk = 0; kk < 64; kk += 4) {
            float4 v = *(const float4*)(src + kk);
            float vv[4] = {v.x, v.y, v.z, v.w};
#pragma unroll
            for (int i = 0; i < 4; i++) {
                __nv_bfloat16 hi = __float2bfloat16(vv[i]);
                __nv_bfloat16 lo = __float2bfloat16(vv[i] - __bfloat162float(hi));
                whi[kk + i] = hi;
                wlo[kk + i] = lo;
            }
        }
    }
    __syncthreads();

    // GEMM roles
    const int mt = wid & 7;        // M-tile: rows mt*16 .. mt*16+15
    const int kh = wid >> 3;       // K-half: 0 -> k 0..127, 1 -> k 128..255
    const int R0 = mt * 16;
    // byte bases for fragment loads
    const char* whiB = smem + SM_WHI;
    const char* wloB = smem + SM_WLO;
    const char* hhiB = smem + SM_HHI;
    const char* hloB = smem + SM_HLO;
    const uint32_t rowA0 = (uint32_t)(R0 + g) * (WS_ * 2);
    const uint32_t rowA1 = (uint32_t)(R0 + g + 8) * (WS_ * 2);
    const uint32_t rowB = (uint32_t)g * (WS_ * 2);
    const uint32_t tgo = (uint32_t)tg * 4;

    const int hh = u & 31, bb = u >> 5;  // epilogue role (u<256)
    float c = 0.0f;
    const size_t xgbase = ((size_t)bg * HCN_ + hc) * 1024 + (size_t)bb * 128 + hh * 4;

    // B-fill role: k = u>>1 (0..255), bb4 = (u&1)*4
    const int kB = u >> 1, bb4 = (u & 1) * 4;
    __nv_bfloat16* hhiW = (__nv_bfloat16*)(smem + SM_HHI);
    __nv_bfloat16* hloW = (__nv_bfloat16*)(smem + SM_HLO);

    for (int t = 0; t < T_; t++) {
        // --- wait for previous step's h from all 8 peers ---
        if (t > 0 && u < 8) {
            volatile unsigned* f = &d_flags[((size_t)(t - 1) * BG_ + bg) * HCN_ + u];
            while (*f != runid) {}
            __threadfence();  // acquire
        }
        __syncthreads();

        // --- B fill: h(k-major in d_hTg) -> hT[b][k] bf16 hi/lo ---
        {
            float4 hv;
            if (t > 0) {
                const float* hp = &d_hTg[((((size_t)((t - 1) & 1)) * BG_ + bg) * H_ + kB) * BC_ + bb4];
                hv = *(const float4*)hp;
            } else {
                hv = make_float4(0.f, 0.f, 0.f, 0.f);
            }
            float vv[4] = {hv.x, hv.y, hv.z, hv.w};
#pragma unroll
            for (int i = 0; i < 4; i++) {
                __nv_bfloat16 hi = __float2bfloat16(vv[i]);
                __nv_bfloat16 lo = __float2bfloat16(vv[i] - __bfloat162float(hi));
                hhiW[(size_t)(bb4 + i) * WS_ + kB] = hi;
                hloW[(size_t)(bb4 + i) * WS_ + kB] = lo;
            }
        }
        __syncthreads();

        // --- xg prefetch (hides DRAM under the GEMM) ---
        float4 xg4 = make_float4(0.f, 0.f, 0.f, 0.f);
        if (u < 256) {
            xg4 = *(const float4*)&d_xg[(size_t)t * (BG_ * HCN_ * 1024) + xgbase];
        }

        // --- GEMM: 8 k-tiles of 16, 3-term bf16 split, f32 accum in regs ---
        float d0 = 0.f, d1 = 0.f, d2 = 0.f, d3 = 0.f;
#pragma unroll
        for (int kt = 0; kt < 8; kt++) {
            uint32_t kb = (uint32_t)(kh * 128 + kt * 16) * 2;  // byte offset of k0
            uint32_t ah0 = *(const uint32_t*)(whiB + rowA0 + kb + tgo);
            uint32_t ah1 = *(const uint32_t*)(whiB + rowA1 + kb + tgo);
            uint32_t ah2 = *(const uint32_t*)(whiB + rowA0 + kb + tgo + 16);
            uint32_t ah3 = *(const uint32_t*)(whiB + rowA1 + kb + tgo + 16);
            uint32_t bh0 = *(const uint32_t*)(hhiB + rowB + kb + tgo);
            uint32_t bh1 = *(const uint32_t*)(hhiB + rowB + kb + tgo + 16);
            uint32_t al0 = *(const uint32_t*)(wloB + rowA0 + kb + tgo);
            uint32_t al1 = *(const uint32_t*)(wloB + rowA1 + kb + tgo);
            uint32_t al2 = *(const uint32_t*)(wloB + rowA0 + kb + tgo + 16);
            uint32_t al3 = *(const uint32_t*)(wloB + rowA1 + kb + tgo + 16);
            uint32_t bl0 = *(const uint32_t*)(hloB + rowB + kb + tgo);
            uint32_t bl1 = *(const uint32_t*)(hloB + rowB + kb + tgo + 16);
            mma16816(d0, d1, d2, d3, ah0, ah1, ah2, ah3, bh0, bh1);
            mma16816(d0, d1, d2, d3, ah0, ah1, ah2, ah3, bl0, bl1);
            mma16816(d0, d1, d2, d3, al0, al1, al2, al3, bh0, bh1);
        }

        // --- store partials: red[kh][b][r], r = R0+g(+8), b = tg*2(+1) ---
        {
            float* rp = &red[(size_t)(kh * 8) * 132];
            rp[(tg * 2 + 0) * 132 + R0 + g] = d0;
            rp[(tg * 2 + 1) * 132 + R0 + g] = d1;
            rp[(tg * 2 + 0) * 132 + R0 + g + 8] = d2;
            rp[(tg * 2 + 1) * 132 + R0 + g + 8] = d3;
        }
        __syncthreads();

        // --- epilogue: thread (hh, bb) -> 4 gates from red[0]+red[1] ---
        if (u < 256) {
            const float* r0p = &red[(size_t)bb * 132 + hh * 4];
            const float* r1p = &red[(size_t)(8 + bb) * 132 + hh * 4];
            float4 p0 = *(const float4*)r0p;
            float4 p1 = *(const float4*)r1p;
            float si = p0.x + p1.x + xg4.x;
            float sf = p0.y + p1.y + xg4.y;
            float sg = p0.z + p1.z + xg4.z;
            float so = p0.w + p1.w + xg4.w;
            float iv = sigm(si);
            float fv = sigm(sf);
            float gv = tanhf(sg);
            float ov = sigm(so);
            c = fv * c + iv * gv;
            float hval = ov * tanhf(c);
            d_rbuf[((size_t)t * B_ + bg * BC_ + bb) * H_ + hc * 32 + hh] = hval;
            d_hTg[((((size_t)(t & 1)) * BG_ + bg) * H_ + hc * 32 + hh) * BC_ + bb] = hval;
        }
        __syncthreads();
        if (u == 0) {
            __threadfence();  // release
            *(volatile unsigned*)&d_flags[((size_t)t * BG_ + bg) * HCN_ + hc] = runid;
        }
    }
}

// ---------------- kernel 3: out = r_out @ W_out^T + b_out ----------------
__global__ __launch_bounds__(256, 2) void k_out(const float* __restrict__ W_out,
                                                const float* __restrict__ b_out,
                                                float* __restrict__ out) {
    extern __shared__ float sm[];
    float* wo = sm;
    float* rs = sm + 64 * 256;
    const int t = blockIdx.x;
    const int u = threadIdx.x;

    for (int i = u; i < 64 * 256 / 4; i += 256)
        *(float4*)&wo[i * 4] = *(const float4*)&W_out[i * 4];

    const int bq = u & 15, oq = u >> 4;
    ull acc[4][4];
#pragma unroll
    for (int j = 0; j < 4; j++)
#pragma unroll
        for (int p = 0; p < 4; p++) acc[j][p] = 0ull;

    const int bs = u >> 1, half = u & 1;
    const float* rsrc = d_rbuf + ((size_t)t * B_ + bs) * H_ + half * 16;
    __syncthreads();

    for (int kc = 0; kc < H_; kc += 32) {
#pragma unroll
        for (int q = 0; q < 4; q++) {
            float4 v = *(const float4*)(rsrc + kc + q * 4);
            int kl = half * 16 + q * 4;
            rs[(kl + 0) * WPAD + bs] = v.x;
            rs[(kl + 1) * WPAD + bs] = v.y;
            rs[(kl + 2) * WPAD + bs] = v.z;
            rs[(kl + 3) * WPAD + bs] = v.w;
        }
        __syncthreads();
#pragma unroll 4
        for (int kk = 0; kk < 32; kk++) {
            int k = kc + kk;
            const float* xr = &rs[kk * WPAD + bq * 8];
            ulonglong2 xa = *(const ulonglong2*)xr;
            ulonglong2 xb = *(const ulonglong2*)(xr + 4);
            ull xp0 = xa.x, xp1 = xa.y, xp2 = xb.x, xp3 = xb.y;
#pragma unroll
            for (int j = 0; j < 4; j++) {
                ull wj = pack2(wo[(oq * 4 + j) * 256 + k]);
                acc[j][0] = ffma2(wj, xp0, acc[j][0]);
                acc[j][1] = ffma2(wj, xp1, acc[j][1]);
                acc[j][2] = ffma2(wj, xp2, acc[j][2]);
                acc[j][3] = ffma2(wj, xp3, acc[j][3]);
            }
        }
        __syncthreads();
    }
#pragma unroll
    for (int j = 0; j < 4; j++) {
        int o = oq * 4 + j;
        float bv = b_out[o];
#pragma unroll
        for (int p = 0; p < 4; p++) {
            float lo, hi;
            unpack2(acc[j][p], lo, hi);
            int b0 = bq * 8 + 2 * p;
            out[((size_t)t * B_ + b0) * OUT_ + o] = lo + bv;
            out[((size_t)t * B_ + b0 + 1) * OUT_ + o] = hi + bv;
        }
    }
}

// ---------------- launcher ----------------
extern "C" void kernel_launch(void* const* d_in, const int* in_sizes, int n_in,
                              void* d_out, int out_size) {
    const float* x     = (const float*)d_in[0];
    const float* W_ih  = (const float*)d_in[1];
    const float* W_hh  = (const float*)d_in[2];
    const float* b_ih  = (const float*)d_in[3];
    const float* b_hh  = (const float*)d_in[4];
    const float* W_out = (const float*)d_in[5];
    const float* b_out = (const float*)d_in[6];
    float* out = (float*)d_out;

    cudaFuncSetAttribute(k_rec, cudaFuncAttributeMaxDynamicSharedMemorySize, REC_SMEM);
    cudaFuncSetAttribute(k_out, cudaFuncAttributeMaxDynamicSharedMemorySize, OUT_SMEM);

    k_init<<<1, 1>>>();
    k_xg<<<dim3(HCN_, T_), 256>>>(x, W_ih, b_ih, b_hh);
    k_rec<<<BG_ * HCN_, 512, REC_SMEM>>>(W_hh);
    k_out<<<T_, 256, OUT_SMEM>>>(W_out, b_out, out);
}

// round 6
// speedup vs baseline: 1.1415x; 1.1415x over previous
#include <cuda_runtime.h>
#include <cuda_bf16.h>
#include <cstdint>
#include <cstddef>

typedef unsigned long long ull;

#define T_   2048
#define B_   128
#define IN_  128
#define H_   256
#define G4_  1024
#define OUT_ 64

#define BG_  16   // batch groups (= clusters)
#define HCN_ 8    // hidden-slice CTAs per batch group (= cluster size)
#define BC_  8    // batches per group

#define WPAD 132  // padded row stride (floats) for fp32 GEMM smem tiles

// ---- k_rec smem layout (bytes). Rows padded to 264 bf16 (528B) ----
#define WS_     264                        // bf16 row stride for W/h tiles
#define SM_WHI  0                          // Whi bf16 [128][264]  (67584 B)
#define SM_WLO  (SM_WHI + 128 * WS_ * 2)   // Wlo bf16 [128][264]
#define SM_BT   (SM_WLO + 128 * WS_ * 2)   // B tiles: 2 parities x (hi+lo)
#define SM_BTSZ (8 * WS_ * 2)              // 4224 B per tile
#define SM_BHI(p) (SM_BT + (p) * (2 * SM_BTSZ))
#define SM_BLO(p) (SM_BT + (p) * (2 * SM_BTSZ) + SM_BTSZ)
#define SM_RED  (SM_BT + 4 * SM_BTSZ)      // red f32 [2][8][132] (8448 B)
#define SM_MBAR (SM_RED + 2 * 8 * 132 * 4) // 2 mbarriers (8 B each)
#define REC_SMEM (SM_MBAR + 64)

#define OUT_SMEM ((64 * 256 + 32 * WPAD) * 4)

// tx bytes arriving at each consumer mbarrier per step:
// 8 source CTAs x 128 even-lanes x 2 stores x 4 B = 8192
#define TX_BYTES 8192

// ---------------- device scratch (static, allocation-free) ----------------
__device__ float d_xg[(size_t)T_ * B_ * G4_];    // 1 GB  [t][bg][hc][bb][col]
__device__ float d_rbuf[(size_t)T_ * B_ * H_];   // 256 MB [t][b][h]

// ---------------- f32x2 helpers ----------------
__device__ __forceinline__ ull pack2(float x) {
    unsigned xi = __float_as_uint(x);
    ull r;
    asm("mov.b64 %0, {%1, %1};" : "=l"(r) : "r"(xi));
    return r;
}
__device__ __forceinline__ ull ffma2(ull a, ull b, ull c) {
    ull d;
    asm("fma.rn.f32x2 %0, %1, %2, %3;" : "=l"(d) : "l"(a), "l"(b), "l"(c));
    return d;
}
__device__ __forceinline__ void unpack2(ull v, float& lo, float& hi) {
    unsigned l, h;
    asm("mov.b64 {%0, %1}, %2;" : "=r"(l), "=r"(h) : "l"(v));
    lo = __uint_as_float(l);
    hi = __uint_as_float(h);
}
__device__ __forceinline__ float sigm(float x) { return 1.0f / (1.0f + __expf(-x)); }

// bf16 mma m16n8k16 row.col, f32 accum (plain HMMA, no arch-a features)
__device__ __forceinline__ void mma16816(float& d0, float& d1, float& d2, float& d3,
                                         uint32_t a0, uint32_t a1, uint32_t a2, uint32_t a3,
                                         uint32_t b0, uint32_t b1) {
    asm volatile(
        "mma.sync.aligned.m16n8k16.row.col.f32.bf16.bf16.f32 "
        "{%0,%1,%2,%3}, {%4,%5,%6,%7}, {%8,%9}, {%0,%1,%2,%3};"
        : "+f"(d0), "+f"(d1), "+f"(d2), "+f"(d3)
        : "r"(a0), "r"(a1), "r"(a2), "r"(a3), "r"(b0), "r"(b1));
}

// ---------------- cluster / mbarrier helpers (sm_90 baseline PTX) ----------------
__device__ __forceinline__ uint32_t smem_u32(const void* p) {
    uint32_t a;
    asm("{ .reg .u64 t; cvta.to.shared.u64 t, %1; cvt.u32.u64 %0, t; }" : "=r"(a) : "l"(p));
    return a;
}
__device__ __forceinline__ uint32_t mapa_u32(uint32_t addr, uint32_t rank) {
    uint32_t r;
    asm("mapa.shared::cluster.u32 %0, %1, %2;" : "=r"(r) : "r"(addr), "r"(rank));
    return r;
}
__device__ __forceinline__ void st_async32(uint32_t daddr, uint32_t val, uint32_t dmbar) {
    asm volatile(
        "st.async.weak.shared::cluster.mbarrier::complete_tx::bytes.b32 [%0], %1, [%2];"
        :: "r"(daddr), "r"(val), "r"(dmbar) : "memory");
}
#define MBAR_INIT(a, c) asm volatile("mbarrier.init.shared.b64 [%0], %1;" :: "r"(a), "r"(c) : "memory")
#define MBAR_EXPECT(a, tx) asm volatile( \
    "mbarrier.arrive.expect_tx.shared.b64 _, [%0], %1;" :: "r"(a), "r"(tx) : "memory")
#define MBAR_WAIT_CL(a, par) do { \
    asm volatile("{\n\t.reg .pred P;\nWAITC_%=:\n\t" \
                 "mbarrier.try_wait.parity.acquire.cluster.shared::cta.b64 P, [%0], %1;\n\t" \
                 "@!P bra WAITC_%=;\n\t}" :: "r"(a), "r"(par) : "memory"); \
} while (0)
#define CLUSTER_SYNC() do { \
    asm volatile("barrier.cluster.arrive.aligned;" ::: "memory"); \
    asm volatile("barrier.cluster.wait.aligned;" ::: "memory"); \
} while (0)

// ---------------- kernel 1: xg = x @ W_ih^T + b_ih + b_hh (permuted) -------
__global__ __launch_bounds__(256, 2) void k_xg(const float* __restrict__ x,
                                               const float* __restrict__ W_ih,
                                               const float* __restrict__ b_ih,
                                               const float* __restrict__ b_hh) {
    __shared__ float xs[32 * WPAD];
    __shared__ float ws[32 * WPAD];
    const int hc = blockIdx.x;
    const int t = blockIdx.y;
    const int u = threadIdx.x;
    const int tm = u & 15;
    const int tn = u >> 4;

    ull acc[8][4];
#pragma unroll
    for (int j = 0; j < 8; j++)
#pragma unroll
        for (int p = 0; p < 4; p++) acc[j][p] = 0ull;

    const int bs = u >> 1, half = u & 1;
    const int colS = u >> 1;
    const int RS = (colS & 3) * H_ + hc * 32 + (colS >> 2);
    const float* xsrc = x + ((size_t)t * B_ + bs) * IN_ + half * 16;
    const float* wsrc = W_ih + (size_t)RS * IN_ + half * 16;

    for (int kc = 0; kc < IN_; kc += 32) {
#pragma unroll
        for (int q = 0; q < 4; q++) {
            float4 v = *(const float4*)(xsrc + kc + q * 4);
            int kl = half * 16 + q * 4;
            xs[(kl + 0) * WPAD + bs] = v.x;
            xs[(kl + 1) * WPAD + bs] = v.y;
            xs[(kl + 2) * WPAD + bs] = v.z;
            xs[(kl + 3) * WPAD + bs] = v.w;
            float4 w = *(const float4*)(wsrc + kc + q * 4);
            ws[(kl + 0) * WPAD + colS] = w.x;
            ws[(kl + 1) * WPAD + colS] = w.y;
            ws[(kl + 2) * WPAD + colS] = w.z;
            ws[(kl + 3) * WPAD + colS] = w.w;
        }
        __syncthreads();
#pragma unroll 8
        for (int kk = 0; kk < 32; kk++) {
            const float* xr = &xs[kk * WPAD + tm * 8];
            ulonglong2 xa = *(const ulonglong2*)xr;
            ulonglong2 xb = *(const ulonglong2*)(xr + 4);
            ull xp0 = xa.x, xp1 = xa.y, xp2 = xb.x, xp3 = xb.y;
            const float* wr = &ws[kk * WPAD + tn * 8];
            float4 wa = *(const float4*)wr;
            float4 wb = *(const float4*)(wr + 4);
            float wv[8] = {wa.x, wa.y, wa.z, wa.w, wb.x, wb.y, wb.z, wb.w};
#pragma unroll
            for (int j = 0; j < 8; j++) {
                ull wj = pack2(wv[j]);
                acc[j][0] = ffma2(wj, xp0, acc[j][0]);
                acc[j][1] = ffma2(wj, xp1, acc[j][1]);
                acc[j][2] = ffma2(wj, xp2, acc[j][2]);
                acc[j][3] = ffma2(wj, xp3, acc[j][3]);
            }
        }
        __syncthreads();
    }
    size_t base = (((size_t)t * BG_ + tm) * HCN_ + hc) * 1024;
#pragma unroll
    for (int j = 0; j < 8; j++) {
        int col = tn * 8 + j;
        int R = (col & 3) * H_ + hc * 32 + (col >> 2);
        float bv = b_ih[R] + b_hh[R];
#pragma unroll
        for (int p = 0; p < 4; p++) {
            float lo, hi;
            unpack2(acc[j][p], lo, hi);
            d_xg[base + (size_t)(2 * p) * 128 + col] = lo + bv;
            d_xg[base + (size_t)(2 * p + 1) * 128 + col] = hi + bv;
        }
    }
}

// ---------------- kernel 2: persistent recurrence (HMMA + cluster DSMEM) -------
// 16 clusters of 8 CTAs. blockIdx.x = bg*8 + hc. CTA owns gate-rows r = hh*4+g
// for hidden units hc*32..+31, batches bg*8..+7.
// h exchange: epilogue threads st.async bf16(hi|lo) pairs directly into all 8
// peers' parity-double-buffered B tiles; consumers wait on tx mbarrier.
__global__ __cluster_dims__(HCN_, 1, 1) __launch_bounds__(512, 1)
void k_rec(const float* __restrict__ W_hh) {
    extern __shared__ char smem[];
    const uint32_t sb = smem_u32(smem);
    float* red = (float*)(smem + SM_RED);   // [2][8][132]

    const int u = threadIdx.x;
    const int wid = u >> 5;
    const int lane = u & 31;
    const int g = lane >> 2, tg = lane & 3;
    const int bg = blockIdx.x >> 3;
    const int hc = blockIdx.x & 7;

    // --- init mbarriers + pre-arm both parities; zero parity-0 B tiles ---
    if (u == 0) {
        MBAR_INIT(sb + SM_MBAR + 0, 1);
        MBAR_INIT(sb + SM_MBAR + 8, 1);
        MBAR_EXPECT(sb + SM_MBAR + 0, TX_BYTES);  // first use: t=2
        MBAR_EXPECT(sb + SM_MBAR + 8, TX_BYTES);  // first use: t=1
    }
    for (int i = u; i < (2 * SM_BTSZ) / 4; i += 512)
        ((uint32_t*)(smem + SM_BT))[i] = 0;       // B(par 0) hi+lo = 0 (h0 = 0)

    // --- stage W slice once: smem row r = hh*4+g <- W_hh row (g*256+hc*32+hh),
    //     split into bf16 hi/lo ---
    {
        int r = u >> 2;
        int k0 = (u & 3) * 64;
        int hhw = r >> 2, gw = r & 3;
        const float* src = W_hh + (size_t)(gw * H_ + hc * 32 + hhw) * H_ + k0;
        __nv_bfloat16* whi = (__nv_bfloat16*)(smem + SM_WHI) + (size_t)r * WS_ + k0;
        __nv_bfloat16* wlo = (__nv_bfloat16*)(smem + SM_WLO) + (size_t)r * WS_ + k0;
#pragma unroll 4
        for (int kk = 0; kk < 64; kk += 4) {
            float4 v = *(const float4*)(src + kk);
            float vv[4] = {v.x, v.y, v.z, v.w};
#pragma unroll
            for (int i = 0; i < 4; i++) {
                __nv_bfloat16 hi = __float2bfloat16(vv[i]);
                __nv_bfloat16 lo = __float2bfloat16(vv[i] - __bfloat162float(hi));
                whi[kk + i] = hi;
                wlo[kk + i] = lo;
            }
        }
    }
    __syncthreads();
    CLUSTER_SYNC();   // peers' mbarriers + zeroed tiles visible before any st.async

    // GEMM roles
    const int mt = wid & 7;        // M-tile: rows mt*16 .. mt*16+15
    const int kh = wid >> 3;       // K-half
    const int R0 = mt * 16;
    const char* whiB = smem + SM_WHI;
    const char* wloB = smem + SM_WLO;
    const uint32_t rowA0 = (uint32_t)(R0 + g) * (WS_ * 2);
    const uint32_t rowA1 = (uint32_t)(R0 + g + 8) * (WS_ * 2);
    const uint32_t rowB = (uint32_t)g * (WS_ * 2);
    const uint32_t tgo = (uint32_t)tg * 4;

    const int hh = u & 31, bb = u >> 5;  // epilogue role (u<256): hh = lane
    float c = 0.0f;
    const size_t xgbase = ((size_t)bg * HCN_ + hc) * 1024 + (size_t)bb * 128 + hh * 4;

    for (int t = 0; t < T_; t++) {
        const int par = t & 1;

        // --- xg prefetch first (DRAM latency overlaps the mbarrier wait) ---
        float4 xg4 = make_float4(0.f, 0.f, 0.f, 0.f);
        if (u < 256) {
            xg4 = *(const float4*)&d_xg[(size_t)t * (BG_ * HCN_ * 1024) + xgbase];
        }

        // --- wait for all 8 peers' h slices (tx-counted mbarrier) ---
        if (t > 0) {
            uint32_t amb = sb + SM_MBAR + par * 8;
            uint32_t ph = (uint32_t)(((t - 1) >> 1) & 1);
            MBAR_WAIT_CL(amb, ph);
            if (u == 0) MBAR_EXPECT(amb, TX_BYTES);  // re-arm for step t+2
        }

        // --- GEMM: 8 k-tiles of 16, 3-term bf16 split, f32 accum in regs ---
        const char* hhiB = smem + SM_BHI(par);
        const char* hloB = smem + SM_BLO(par);
        float d0 = 0.f, d1 = 0.f, d2 = 0.f, d3 = 0.f;
#pragma unroll
        for (int kt = 0; kt < 8; kt++) {
            uint32_t kb = (uint32_t)(kh * 128 + kt * 16) * 2;
            uint32_t ah0 = *(const uint32_t*)(whiB + rowA0 + kb + tgo);
            uint32_t ah1 = *(const uint32_t*)(whiB + rowA1 + kb + tgo);
            uint32_t ah2 = *(const uint32_t*)(whiB + rowA0 + kb + tgo + 16);
            uint32_t ah3 = *(const uint32_t*)(whiB + rowA1 + kb + tgo + 16);
            uint32_t bh0 = *(const uint32_t*)(hhiB + rowB + kb + tgo);
            uint32_t bh1 = *(const uint32_t*)(hhiB + rowB + kb + tgo + 16);
            uint32_t al0 = *(const uint32_t*)(wloB + rowA0 + kb + tgo);
            uint32_t al1 = *(const uint32_t*)(wloB + rowA1 + kb + tgo);
            uint32_t al2 = *(const uint32_t*)(wloB + rowA0 + kb + tgo + 16);
            uint32_t al3 = *(const uint32_t*)(wloB + rowA1 + kb + tgo + 16);
            uint32_t bl0 = *(const uint32_t*)(hloB + rowB + kb + tgo);
            uint32_t bl1 = *(const uint32_t*)(hloB + rowB + kb + tgo + 16);
            mma16816(d0, d1, d2, d3, ah0, ah1, ah2, ah3, bh0, bh1);
            mma16816(d0, d1, d2, d3, ah0, ah1, ah2, ah3, bl0, bl1);
            mma16816(d0, d1, d2, d3, al0, al1, al2, al3, bh0, bh1);
        }

        // --- store partials: red[kh][b][r] ---
        {
            float* rp = &red[(size_t)(kh * 8) * 132];
            rp[(tg * 2 + 0) * 132 + R0 + g] = d0;
            rp[(tg * 2 + 1) * 132 + R0 + g] = d1;
            rp[(tg * 2 + 0) * 132 + R0 + g + 8] = d2;
            rp[(tg * 2 + 1) * 132 + R0 + g + 8] = d3;
        }
        __syncthreads();

        // --- epilogue: thread (hh, bb) -> 4 gates; then publish h via DSMEM ---
        if (u < 256) {
            const float* r0p = &red[(size_t)bb * 132 + hh * 4];
            const float* r1p = &red[(size_t)(8 + bb) * 132 + hh * 4];
            float4 p0 = *(const float4*)r0p;
            float4 p1 = *(const float4*)r1p;
            float si = p0.x + p1.x + xg4.x;
            float sf = p0.y + p1.y + xg4.y;
            float sg = p0.z + p1.z + xg4.z;
            float so = p0.w + p1.w + xg4.w;
            float iv = sigm(si);
            float fv = sigm(sf);
            float gv = tanhf(sg);
            float ov = sigm(so);
            c = fv * c + iv * gv;
            float hval = ov * tanhf(c);
            d_rbuf[((size_t)t * B_ + bg * BC_ + bb) * H_ + hc * 32 + hh] = hval;

            // split h into bf16 hi/lo and pack adjacent-k pairs
            __nv_bfloat16 bh = __float2bfloat16(hval);
            __nv_bfloat16 bl = __float2bfloat16(hval - __bfloat162float(bh));
            unsigned hiw = (unsigned)__bfloat16_as_ushort(bh);
            unsigned low = (unsigned)__bfloat16_as_ushort(bl);
            unsigned hin = __shfl_down_sync(0xFFFFFFFFu, hiw, 1);
            unsigned lon = __shfl_down_sync(0xFFFFFFFFu, low, 1);
            if (((lane & 1) == 0) && t < T_ - 1) {
                unsigned hi2 = hiw | (hin << 16);
                unsigned lo2 = low | (lon << 16);
                const int parw = (t + 1) & 1;
                uint32_t offB = ((uint32_t)bb * WS_ + (uint32_t)(hc * 32 + hh)) * 2;
                uint32_t ahi = sb + SM_BHI(parw) + offB;
                uint32_t alo = sb + SM_BLO(parw) + offB;
                uint32_t amb = sb + SM_MBAR + parw * 8;
#pragma unroll
                for (int r = 0; r < 8; r++) {
                    uint32_t dh = mapa_u32(ahi, (uint32_t)r);
                    uint32_t dl = mapa_u32(alo, (uint32_t)r);
                    uint32_t dm = mapa_u32(amb, (uint32_t)r);
                    st_async32(dh, hi2, dm);
                    st_async32(dl, lo2, dm);
                }
            }
        }
    }
}

// ---------------- kernel 3: out = r_out @ W_out^T + b_out ----------------
__global__ __launch_bounds__(256, 2) void k_out(const float* __restrict__ W_out,
                                                const float* __restrict__ b_out,
                                                float* __restrict__ out) {
    extern __shared__ float sm[];
    float* wo = sm;
    float* rs = sm + 64 * 256;
    const int t = blockIdx.x;
    const int u = threadIdx.x;

    for (int i = u; i < 64 * 256 / 4; i += 256)
        *(float4*)&wo[i * 4] = *(const float4*)&W_out[i * 4];

    const int bq = u & 15, oq = u >> 4;
    ull acc[4][4];
#pragma unroll
    for (int j = 0; j < 4; j++)
#pragma unroll
        for (int p = 0; p < 4; p++) acc[j][p] = 0ull;

    const int bs = u >> 1, half = u & 1;
    const float* rsrc = d_rbuf + ((size_t)t * B_ + bs) * H_ + half * 16;
    __syncthreads();

    for (int kc = 0; kc < H_; kc += 32) {
#pragma unroll
        for (int q = 0; q < 4; q++) {
            float4 v = *(const float4*)(rsrc + kc + q * 4);
            int kl = half * 16 + q * 4;
            rs[(kl + 0) * WPAD + bs] = v.x;
            rs[(kl + 1) * WPAD + bs] = v.y;
            rs[(kl + 2) * WPAD + bs] = v.z;
            rs[(kl + 3) * WPAD + bs] = v.w;
        }
        __syncthreads();
#pragma unroll 4
        for (int kk = 0; kk < 32; kk++) {
            int k = kc + kk;
            const float* xr = &rs[kk * WPAD + bq * 8];
            ulonglong2 xa = *(const ulonglong2*)xr;
            ulonglong2 xb = *(const ulonglong2*)(xr + 4);
            ull xp0 = xa.x, xp1 = xa.y, xp2 = xb.x, xp3 = xb.y;
#pragma unroll
            for (int j = 0; j < 4; j++) {
                ull wj = pack2(wo[(oq * 4 + j) * 256 + k]);
                acc[j][0] = ffma2(wj, xp0, acc[j][0]);
                acc[j][1] = ffma2(wj, xp1, acc[j][1]);
                acc[j][2] = ffma2(wj, xp2, acc[j][2]);
                acc[j][3] = ffma2(wj, xp3, acc[j][3]);
            }
        }
        __syncthreads();
    }
#pragma unroll
    for (int j = 0; j < 4; j++) {
        int o = oq * 4 + j;
        float bv = b_out[o];
#pragma unroll
        for (int p = 0; p < 4; p++) {
            float lo, hi;
            unpack2(acc[j][p], lo, hi);
            int b0 = bq * 8 + 2 * p;
            out[((size_t)t * B_ + b0) * OUT_ + o] = lo + bv;
            out[((size_t)t * B_ + b0 + 1) * OUT_ + o] = hi + bv;
        }
    }
}

// ---------------- launcher ----------------
extern "C" void kernel_launch(void* const* d_in, const int* in_sizes, int n_in,
                              void* d_out, int out_size) {
    const float* x     = (const float*)d_in[0];
    const float* W_ih  = (const float*)d_in[1];
    const float* W_hh  = (const float*)d_in[2];
    const float* b_ih  = (const float*)d_in[3];
    const float* b_hh  = (const float*)d_in[4];
    const float* W_out = (const float*)d_in[5];
    const float* b_out = (const float*)d_in[6];
    float* out = (float*)d_out;

    cudaFuncSetAttribute(k_rec, cudaFuncAttributeMaxDynamicSharedMemorySize, REC_SMEM);
    cudaFuncSetAttribute(k_out, cudaFuncAttributeMaxDynamicSharedMemorySize, OUT_SMEM);

    k_xg<<<dim3(HCN_, T_), 256>>>(x, W_ih, b_ih, b_hh);
    k_rec<<<BG_ * HCN_, 512, REC_SMEM>>>(W_hh);
    k_out<<<T_, 256, OUT_SMEM>>>(W_out, b_out, out);
}

// round 7
// speedup vs baseline: 1.5236x; 1.3347x over previous
#include <cuda_runtime.h>
#include <cuda_bf16.h>
#include <cstdint>
#include <cstddef>

typedef unsigned long long ull;

#define T_   2048
#define B_   128
#define IN_  128
#define H_   256
#define G4_  1024
#define OUT_ 64

#define BG_  16   // batch groups (= clusters)
#define HCN_ 8    // hidden-slice CTAs per cluster
#define BC_  8    // batches per group

#define WPAD 132  // padded row stride (floats) for fp32 GEMM smem tiles

// ---- k_rec smem layout (bytes) ----
// B2 tile: [8 b][132 kp][{hi2,lo2} u32 pair] = 8448 B per parity
#define SM_B2SZ   8448
#define SM_B2(p)  ((p) * SM_B2SZ)
#define SM_RED    (2 * SM_B2SZ)                 // red f32 [2][8][132] = 8448 B
#define SM_MBAR   (SM_RED + 2 * 8 * 132 * 4)
#define REC_SMEM  (SM_MBAR + 64)

#define OUT_SMEM ((64 * 256 + 32 * WPAD) * 4)

// tx bytes per consumer mbarrier per step: 8 CTAs x 128 even-lanes x 8 B
#define TX_BYTES 8192

// ---------------- device scratch ----------------
__device__ float d_xg[(size_t)T_ * B_ * G4_];    // [t][bg][hc][bb][col]
__device__ float d_rbuf[(size_t)T_ * B_ * H_];   // [t][b][h]

// ---------------- f32x2 helpers ----------------
__device__ __forceinline__ ull pack2(float x) {
    unsigned xi = __float_as_uint(x);
    ull r;
    asm("mov.b64 %0, {%1, %1};" : "=l"(r) : "r"(xi));
    return r;
}
__device__ __forceinline__ ull ffma2(ull a, ull b, ull c) {
    ull d;
    asm("fma.rn.f32x2 %0, %1, %2, %3;" : "=l"(d) : "l"(a), "l"(b), "l"(c));
    return d;
}
__device__ __forceinline__ void unpack2(ull v, float& lo, float& hi) {
    unsigned l, h;
    asm("mov.b64 {%0, %1}, %2;" : "=r"(l), "=r"(h) : "l"(v));
    lo = __uint_as_float(l);
    hi = __uint_as_float(h);
}

// fast branch-free activations (MUFU-based, ~1e-6 rel err)
__device__ __forceinline__ float rcpa(float x) {
    float r;
    asm("rcp.approx.f32 %0, %1;" : "=f"(r) : "f"(x));
    return r;
}
__device__ __forceinline__ float sigf(float x) { return rcpa(1.0f + __expf(-x)); }
__device__ __forceinline__ float tanhfa(float x) { return 1.0f - 2.0f * rcpa(1.0f + __expf(2.0f * x)); }

// bf16 mma m16n8k16 row.col, f32 accum
__device__ __forceinline__ void mma16816(float* d,
                                         uint32_t a0, uint32_t a1, uint32_t a2, uint32_t a3,
                                         uint32_t b0, uint32_t b1) {
    asm volatile(
        "mma.sync.aligned.m16n8k16.row.col.f32.bf16.bf16.f32 "
        "{%0,%1,%2,%3}, {%4,%5,%6,%7}, {%8,%9}, {%0,%1,%2,%3};"
        : "+f"(d[0]), "+f"(d[1]), "+f"(d[2]), "+f"(d[3])
        : "r"(a0), "r"(a1), "r"(a2), "r"(a3), "r"(b0), "r"(b1));
}

// pack two fp32 into bf16 hi-word + residual lo-word
__device__ __forceinline__ void split2(float a, float b, uint32_t& hi, uint32_t& lo) {
    __nv_bfloat16 ha = __float2bfloat16(a), hb = __float2bfloat16(b);
    hi = (uint32_t)__bfloat16_as_ushort(ha) | ((uint32_t)__bfloat16_as_ushort(hb) << 16);
    __nv_bfloat16 la = __float2bfloat16(a - __bfloat162float(ha));
    __nv_bfloat16 lb = __float2bfloat16(b - __bfloat162float(hb));
    lo = (uint32_t)__bfloat16_as_ushort(la) | ((uint32_t)__bfloat16_as_ushort(lb) << 16);
}

// ---------------- cluster / mbarrier helpers ----------------
__device__ __forceinline__ uint32_t smem_u32(const void* p) {
    uint32_t a;
    asm("{ .reg .u64 t; cvta.to.shared.u64 t, %1; cvt.u32.u64 %0, t; }" : "=r"(a) : "l"(p));
    return a;
}
__device__ __forceinline__ uint32_t mapa_u32(uint32_t addr, uint32_t rank) {
    uint32_t r;
    asm("mapa.shared::cluster.u32 %0, %1, %2;" : "=r"(r) : "r"(addr), "r"(rank));
    return r;
}
__device__ __forceinline__ void st_async64(uint32_t daddr, ull val, uint32_t dmbar) {
    asm volatile(
        "st.async.weak.shared::cluster.mbarrier::complete_tx::bytes.b64 [%0], %1, [%2];"
        :: "r"(daddr), "l"(val), "r"(dmbar) : "memory");
}
#define MBAR_INIT(a, c) asm volatile("mbarrier.init.shared.b64 [%0], %1;" :: "r"(a), "r"(c) : "memory")
#define MBAR_EXPECT(a, tx) asm volatile( \
    "mbarrier.arrive.expect_tx.shared.b64 _, [%0], %1;" :: "r"(a), "r"(tx) : "memory")
#define MBAR_WAIT_CL(a, par) do { \
    asm volatile("{\n\t.reg .pred P;\nWAITC_%=:\n\t" \
                 "mbarrier.try_wait.parity.acquire.cluster.shared::cta.b64 P, [%0], %1;\n\t" \
                 "@!P bra WAITC_%=;\n\t}" :: "r"(a), "r"(par) : "memory"); \
} while (0)
#define CLUSTER_SYNC() do { \
    asm volatile("barrier.cluster.arrive.aligned;" ::: "memory"); \
    asm volatile("barrier.cluster.wait.aligned;" ::: "memory"); \
} while (0)

// ---------------- kernel 1: xg = x @ W_ih^T + b_ih + b_hh (permuted) -------
__global__ __launch_bounds__(256, 2) void k_xg(const float* __restrict__ x,
                                               const float* __restrict__ W_ih,
                                               const float* __restrict__ b_ih,
                                               const float* __restrict__ b_hh) {
    __shared__ float xs[32 * WPAD];
    __shared__ float ws[32 * WPAD];
    const int hc = blockIdx.x;
    const int t = blockIdx.y;
    const int u = threadIdx.x;
    const int tm = u & 15;
    const int tn = u >> 4;

    ull acc[8][4];
#pragma unroll
    for (int j = 0; j < 8; j++)
#pragma unroll
        for (int p = 0; p < 4; p++) acc[j][p] = 0ull;

    const int bs = u >> 1, half = u & 1;
    const int colS = u >> 1;
    const int RS = (colS & 3) * H_ + hc * 32 + (colS >> 2);
    const float* xsrc = x + ((size_t)t * B_ + bs) * IN_ + half * 16;
    const float* wsrc = W_ih + (size_t)RS * IN_ + half * 16;

    for (int kc = 0; kc < IN_; kc += 32) {
#pragma unroll
        for (int q = 0; q < 4; q++) {
            float4 v = *(const float4*)(xsrc + kc + q * 4);
            int kl = half * 16 + q * 4;
            xs[(kl + 0) * WPAD + bs] = v.x;
            xs[(kl + 1) * WPAD + bs] = v.y;
            xs[(kl + 2) * WPAD + bs] = v.z;
            xs[(kl + 3) * WPAD + bs] = v.w;
            float4 w = *(const float4*)(wsrc + kc + q * 4);
            ws[(kl + 0) * WPAD + colS] = w.x;
            ws[(kl + 1) * WPAD + colS] = w.y;
            ws[(kl + 2) * WPAD + colS] = w.z;
            ws[(kl + 3) * WPAD + colS] = w.w;
        }
        __syncthreads();
#pragma unroll 8
        for (int kk = 0; kk < 32; kk++) {
            const float* xr = &xs[kk * WPAD + tm * 8];
            ulonglong2 xa = *(const ulonglong2*)xr;
            ulonglong2 xb = *(const ulonglong2*)(xr + 4);
            ull xp0 = xa.x, xp1 = xa.y, xp2 = xb.x, xp3 = xb.y;
            const float* wr = &ws[kk * WPAD + tn * 8];
            float4 wa = *(const float4*)wr;
            float4 wb = *(const float4*)(wr + 4);
            float wv[8] = {wa.x, wa.y, wa.z, wa.w, wb.x, wb.y, wb.z, wb.w};
#pragma unroll
            for (int j = 0; j < 8; j++) {
                ull wj = pack2(wv[j]);
                acc[j][0] = ffma2(wj, xp0, acc[j][0]);
                acc[j][1] = ffma2(wj, xp1, acc[j][1]);
                acc[j][2] = ffma2(wj, xp2, acc[j][2]);
                acc[j][3] = ffma2(wj, xp3, acc[j][3]);
            }
        }
        __syncthreads();
    }
    size_t base = (((size_t)t * BG_ + tm) * HCN_ + hc) * 1024;
#pragma unroll
    for (int j = 0; j < 8; j++) {
        int col = tn * 8 + j;
        int R = (col & 3) * H_ + hc * 32 + (col >> 2);
        float bv = b_ih[R] + b_hh[R];
#pragma unroll
        for (int p = 0; p < 4; p++) {
            float lo, hi;
            unpack2(acc[j][p], lo, hi);
            d_xg[base + (size_t)(2 * p) * 128 + col] = lo + bv;
            d_xg[base + (size_t)(2 * p + 1) * 128 + col] = hi + bv;
        }
    }
}

// ---------------- kernel 2: persistent recurrence ----------------
// 16 clusters of 8 CTAs. W fragments live in REGISTERS (loaded once from GMEM).
// Per step: D[128x8] = W @ h via 3-term bf16 mma.sync; h exchanged via st.async.b64
// into parity-double-buffered interleaved {hi,lo} B tiles.
__global__ __cluster_dims__(HCN_, 1, 1) __launch_bounds__(512, 1)
void k_rec(const float* __restrict__ W_hh) {
    extern __shared__ char smem[];
    const uint32_t sb = smem_u32(smem);
    float* red = (float*)(smem + SM_RED);   // [2][8][132]

    const int u = threadIdx.x;
    const int wid = u >> 5;
    const int lane = u & 31;
    const int g = lane >> 2, tg = lane & 3;
    const int bg = blockIdx.x >> 3;
    const int hc = blockIdx.x & 7;

    // --- mbarriers: init + pre-arm both parities ---
    if (u == 0) {
        MBAR_INIT(sb + SM_MBAR + 0, 1);
        MBAR_INIT(sb + SM_MBAR + 8, 1);
        MBAR_EXPECT(sb + SM_MBAR + 0, TX_BYTES);  // first completes for t=2
        MBAR_EXPECT(sb + SM_MBAR + 8, TX_BYTES);  // first completes for t=1
    }
    // zero parity-0 B tile (h0 = 0)
    for (int i = u; i < SM_B2SZ / 4; i += 512)
        ((uint32_t*)(smem + SM_B2(0)))[i] = 0;

    // --- hoisted DSMEM base addresses ---
    uint32_t rbase[HCN_];
#pragma unroll
    for (int r = 0; r < HCN_; r++) rbase[r] = mapa_u32(sb, (uint32_t)r);

    // --- GEMM roles; W fragments -> registers (once) ---
    const int mt = wid & 7;        // M-tile rows mt*16..+15
    const int kh = wid >> 3;       // K-half
    const int R0 = mt * 16;

    uint32_t ahi[8][4], alo[8][4];
#pragma unroll
    for (int kt = 0; kt < 8; kt++) {
        int kbase = kh * 128 + kt * 16 + tg * 2;
#pragma unroll
        for (int p = 0; p < 4; p++) {
            int rs = R0 + g + (p & 1) * 8;
            int kk = kbase + (p >> 1) * 8;
            int gate = rs & 3, hw = rs >> 2;
            const float* wp = W_hh + (size_t)(gate * H_ + hc * 32 + hw) * H_ + kk;
            float2 v = *(const float2*)wp;
            split2(v.x, v.y, ahi[kt][p], alo[kt][p]);
        }
    }
    __syncthreads();
    CLUSTER_SYNC();   // mbarriers + zeroed tiles visible cluster-wide

    const int bb = wid - 8;        // epilogue role (wid>=8): batch bb, hidden hh=lane
    const int hh = lane;
    float c = 0.0f;
    const size_t xgbase = ((size_t)bg * HCN_ + hc) * 1024 + (size_t)(wid >= 8 ? bb : 0) * 128 + hh * 4;

    for (int t = 0; t < T_; t++) {
        const int par = t & 1;

        // --- xg prefetch (epilogue warps; DRAM latency hides under wait+GEMM) ---
        float4 xg4 = make_float4(0.f, 0.f, 0.f, 0.f);
        if (wid >= 8) {
            xg4 = *(const float4*)&d_xg[(size_t)t * (BG_ * HCN_ * 1024) + xgbase];
        }

        // --- wait for all 8 peers' h (tx-counted mbarrier), re-arm for t+2 ---
        if (t > 0) {
            uint32_t amb = sb + SM_MBAR + par * 8;
            uint32_t ph = (uint32_t)(((t - 1) >> 1) & 1);
            MBAR_WAIT_CL(amb, ph);
            if (u == 0) MBAR_EXPECT(amb, TX_BYTES);
        }

        // --- GEMM: 8 kt; 3 independent accumulator chains; A-frags from regs ---
        const char* b2B = smem + SM_B2(par);
        float dA[4] = {0.f, 0.f, 0.f, 0.f};
        float dB4[4] = {0.f, 0.f, 0.f, 0.f};
        float dC[4] = {0.f, 0.f, 0.f, 0.f};
#pragma unroll
        for (int kt = 0; kt < 8; kt++) {
            int kp0 = kh * 64 + kt * 8;
            ull w0 = *(const ull*)(b2B + ((size_t)g * 132 + kp0 + tg) * 8);
            ull w1 = *(const ull*)(b2B + ((size_t)g * 132 + kp0 + tg + 4) * 8);
            uint32_t bh0 = (uint32_t)w0, bl0 = (uint32_t)(w0 >> 32);
            uint32_t bh1 = (uint32_t)w1, bl1 = (uint32_t)(w1 >> 32);
            mma16816(dA, ahi[kt][0], ahi[kt][1], ahi[kt][2], ahi[kt][3], bh0, bh1);
            mma16816(dB4, ahi[kt][0], ahi[kt][1], ahi[kt][2], ahi[kt][3], bl0, bl1);
            mma16816(dC, alo[kt][0], alo[kt][1], alo[kt][2], alo[kt][3], bh0, bh1);
        }
        float d0 = dA[0] + dB4[0] + dC[0];
        float d1 = dA[1] + dB4[1] + dC[1];
        float d2 = dA[2] + dB4[2] + dC[2];
        float d3 = dA[3] + dB4[3] + dC[3];

        // --- store partials: red[kh][b][r] ---
        {
            float* rp = &red[(size_t)(kh * 8) * 132];
            rp[(tg * 2 + 0) * 132 + R0 + g] = d0;
            rp[(tg * 2 + 1) * 132 + R0 + g] = d1;
            rp[(tg * 2 + 0) * 132 + R0 + g + 8] = d2;
            rp[(tg * 2 + 1) * 132 + R0 + g + 8] = d3;
        }
        __syncthreads();

        // --- epilogue (warps 8-15 = arbiter-priority): gates, state, publish ---
        if (wid >= 8) {
            const float* r0p = &red[(size_t)bb * 132 + hh * 4];
            const float* r1p = &red[(size_t)(8 + bb) * 132 + hh * 4];
            float4 p0 = *(const float4*)r0p;
            float4 p1 = *(const float4*)r1p;
            float si = p0.x + p1.x + xg4.x;
            float sf = p0.y + p1.y + xg4.y;
            float sg = p0.z + p1.z + xg4.z;
            float so = p0.w + p1.w + xg4.w;
            float iv = sigf(si);
            float fv = sigf(sf);
            float gv = tanhfa(sg);
            float ov = sigf(so);
            c = fv * c + iv * gv;
            float hval = ov * tanhfa(c);

            // publish h (bf16 hi/lo, k-pair packed) to all 8 peers FIRST
            __nv_bfloat16 bh = __float2bfloat16(hval);
            __nv_bfloat16 bl = __float2bfloat16(hval - __bfloat162float(bh));
            unsigned hiw = (unsigned)__bfloat16_as_ushort(bh);
            unsigned low = (unsigned)__bfloat16_as_ushort(bl);
            unsigned hin = __shfl_down_sync(0xFFFFFFFFu, hiw, 1);
            unsigned lon = __shfl_down_sync(0xFFFFFFFFu, low, 1);
            if (((lane & 1) == 0) && t < T_ - 1) {
                ull v = (ull)(hiw | (hin << 16)) | ((ull)(low | (lon << 16)) << 32);
                const int parw = (t + 1) & 1;
                uint32_t offD = (uint32_t)SM_B2(parw)
                              + ((uint32_t)bb * 132 + (uint32_t)((hc * 32 + hh) >> 1)) * 8;
                uint32_t offM = (uint32_t)SM_MBAR + (uint32_t)parw * 8;
#pragma unroll
                for (int r = 0; r < HCN_; r++) {
                    st_async64(rbase[r] + offD, v, rbase[r] + offM);
                }
            }
            // then the (off-critical-path) DRAM store
            d_rbuf[((size_t)t * B_ + bg * BC_ + bb) * H_ + hc * 32 + hh] = hval;
        }
    }
    CLUSTER_SYNC();
}

// ---------------- kernel 3: out = r_out @ W_out^T + b_out ----------------
__global__ __launch_bounds__(256, 2) void k_out(const float* __restrict__ W_out,
                                                const float* __restrict__ b_out,
                                                float* __restrict__ out) {
    extern __shared__ float sm[];
    float* wo = sm;
    float* rs = sm + 64 * 256;
    const int t = blockIdx.x;
    const int u = threadIdx.x;

    for (int i = u; i < 64 * 256 / 4; i += 256)
        *(float4*)&wo[i * 4] = *(const float4*)&W_out[i * 4];

    const int bq = u & 15, oq = u >> 4;
    ull acc[4][4];
#pragma unroll
    for (int j = 0; j < 4; j++)
#pragma unroll
        for (int p = 0; p < 4; p++) acc[j][p] = 0ull;

    const int bs = u >> 1, half = u & 1;
    const float* rsrc = d_rbuf + ((size_t)t * B_ + bs) * H_ + half * 16;
    __syncthreads();

    for (int kc = 0; kc < H_; kc += 32) {
#pragma unroll
        for (int q = 0; q < 4; q++) {
            float4 v = *(const float4*)(rsrc + kc + q * 4);
            int kl = half * 16 + q * 4;
            rs[(kl + 0) * WPAD + bs] = v.x;
            rs[(kl + 1) * WPAD + bs] = v.y;
            rs[(kl + 2) * WPAD + bs] = v.z;
            rs[(kl + 3) * WPAD + bs] = v.w;
        }
        __syncthreads();
#pragma unroll 4
        for (int kk = 0; kk < 32; kk++) {
            int k = kc + kk;
            const float* xr = &rs[kk * WPAD + bq * 8];
            ulonglong2 xa = *(const ulonglong2*)xr;
            ulonglong2 xb = *(const ulonglong2*)(xr + 4);
            ull xp0 = xa.x, xp1 = xa.y, xp2 = xb.x, xp3 = xb.y;
#pragma unroll
            for (int j = 0; j < 4; j++) {
                ull wj = pack2(wo[(oq * 4 + j) * 256 + k]);
                acc[j][0] = ffma2(wj, xp0, acc[j][0]);
                acc[j][1] = ffma2(wj, xp1, acc[j][1]);
                acc[j][2] = ffma2(wj, xp2, acc[j][2]);
                acc[j][3] = ffma2(wj, xp3, acc[j][3]);
            }
        }
        __syncthreads();
    }
#pragma unroll
    for (int j = 0; j < 4; j++) {
        int o = oq * 4 + j;
        float bv = b_out[o];
#pragma unroll
        for (int p = 0; p < 4; p++) {
            float lo, hi;
            unpack2(acc[j][p], lo, hi);
            int b0 = bq * 8 + 2 * p;
            out[((size_t)t * B_ + b0) * OUT_ + o] = lo + bv;
            out[((size_t)t * B_ + b0 + 1) * OUT_ + o] = hi + bv;
        }
    }
}

// ---------------- launcher ----------------
extern "C" void kernel_launch(void* const* d_in, const int* in_sizes, int n_in,
                              void* d_out, int out_size) {
    const float* x     = (const float*)d_in[0];
    const float* W_ih  = (const float*)d_in[1];
    const float* W_hh  = (const float*)d_in[2];
    const float* b_ih  = (const float*)d_in[3];
    const float* b_hh  = (const float*)d_in[4];
    const float* W_out = (const float*)d_in[5];
    const float* b_out = (const float*)d_in[6];
    float* out = (float*)d_out;

    cudaFuncSetAttribute(k_rec, cudaFuncAttributeMaxDynamicSharedMemorySize, REC_SMEM);
    cudaFuncSetAttribute(k_out, cudaFuncAttributeMaxDynamicSharedMemorySize, OUT_SMEM);

    k_xg<<<dim3(HCN_, T_), 256>>>(x, W_ih, b_ih, b_hh);
    k_rec<<<BG_ * HCN_, 512, REC_SMEM>>>(W_hh);
    k_out<<<T_, 256, OUT_SMEM>>>(W_out, b_out, out);
}